// round 8
// baseline (speedup 1.0000x reference)
#include <cuda_runtime.h>

// Depthwise 3x3 conv with hard-one-hot kernel == pure spatial shift, zero pad:
//   out[b,c,h,w] = x[b,c, h+dy, w+dx],  (dy,dx) = argmax(|weight|) - 1
//
// Persistent single-wave grid-stride kernel: 1184 blocks (148 SMs x 8),
// one warp handles one image row per iteration via a single 256-bit
// ld/st.global.v8.f32 per lane. Horizontal +-1 shift fixed with one register
// shuffle (value shuffled past lane 0/31 is exactly the zero padding).
// Argmax computed once per block (amortized over ~220 rows).

#define NROWS   262144          // 16*64*256*256 / 256
#define NBLOCKS 1184            // 148 SMs * 8 resident blocks
#define WARPS_TOTAL (NBLOCKS * 8)

__global__ __launch_bounds__(256) void shift_row_persist_kernel(
    const float* __restrict__ x, const float* __restrict__ w9,
    float* __restrict__ out)
{
    __shared__ int2 s_shift;
    if (threadIdx.x == 0) {
        float best = -1.0f;
        int bi = 0;
        #pragma unroll
        for (int i = 0; i < 9; ++i) {
            float a = fabsf(w9[i]);
            if (a > best) { best = a; bi = i; }   // first occurrence wins (jnp.argmax)
        }
        s_shift = make_int2(bi / 3 - 1, bi % 3 - 1);
    }
    __syncthreads();
    const int dy = s_shift.x;
    const int dx = s_shift.y;

    const int warp0 = (blockIdx.x * blockDim.x + threadIdx.x) >> 5;
    const int lane  = threadIdx.x & 31;

    for (int gw = warp0; gw < NROWS; gw += WARPS_TOTAL) {
        const int h  = gw & 255;
        const int sh = h + dy;
        const size_t plane = (size_t)(gw >> 8);

        float o0, o1, o2, o3, o4, o5, o6, o7;
        if ((unsigned)sh < 256u) {             // warp-uniform
            const float* src = x + ((plane << 8) + (size_t)sh) * 256 + (lane << 3);
            float a0, a1, a2, a3, a4, a5, a6, a7;
            asm volatile("ld.global.nc.v8.f32 {%0,%1,%2,%3,%4,%5,%6,%7}, [%8];"
                         : "=f"(a0), "=f"(a1), "=f"(a2), "=f"(a3),
                           "=f"(a4), "=f"(a5), "=f"(a6), "=f"(a7)
                         : "l"(src));
            if (dx == 0) {
                o0 = a0; o1 = a1; o2 = a2; o3 = a3;
                o4 = a4; o5 = a5; o6 = a6; o7 = a7;
            } else if (dx > 0) {
                float nxt = __shfl_down_sync(0xffffffffu, a0, 1);
                if (lane == 31) nxt = 0.0f;    // col 256 -> zero pad
                o0 = a1; o1 = a2; o2 = a3; o3 = a4;
                o4 = a5; o5 = a6; o6 = a7; o7 = nxt;
            } else {
                float prv = __shfl_up_sync(0xffffffffu, a7, 1);
                if (lane == 0) prv = 0.0f;     // col -1 -> zero pad
                o0 = prv; o1 = a0; o2 = a1; o3 = a2;
                o4 = a3; o5 = a4; o6 = a5; o7 = a6;
            }
        } else {
            o0 = o1 = o2 = o3 = o4 = o5 = o6 = o7 = 0.0f;
        }

        float* dst = out + ((size_t)gw << 8) + (lane << 3);
        asm volatile("st.global.v8.f32 [%0], {%1,%2,%3,%4,%5,%6,%7,%8};"
                     :: "l"(dst),
                        "f"(o0), "f"(o1), "f"(o2), "f"(o3),
                        "f"(o4), "f"(o5), "f"(o6), "f"(o7)
                     : "memory");
    }
}

extern "C" void kernel_launch(void* const* d_in, const int* in_sizes, int n_in,
                              void* d_out, int out_size) {
    const float* x = (const float*)d_in[0];
    const float* w = (const float*)d_in[1];
    float* out = (float*)d_out;

    shift_row_persist_kernel<<<NBLOCKS, 256>>>(x, w, out);
}

// round 12
// speedup vs baseline: 1.1276x; 1.1276x over previous
#include <cuda_runtime.h>

// FINAL (session-best, R2 structure):
// Depthwise 3x3 conv with hard-one-hot kernel == pure spatial shift, zero pad:
//   out[b,c,h,w] = x[b,c, h+dy, w+dx],  (dy,dx) = argmax(|weight|) - 1
//
// One warp per image row (W=256 -> 8 floats/lane = 2 aligned float4).
// Horizontal shift handled by register shuffle; the element that shuffles in
// past lane 0 / lane 31 is exactly the zero-padding value. All loads/stores
// are aligned 128-bit => perfect sector efficiency. Argmax once per block.
// Measured: 75.3us kernel, 80.8% DRAM-active, 6.4 TB/s — at the HBM
// mixed-stream ceiling (R3/R4/R6/R7/R8 probes: MLP x2, cache hints, v8
// accesses, persistent grid all neutral-or-worse).

__global__ __launch_bounds__(256) void shift_row_kernel(
    const float* __restrict__ x, const float* __restrict__ w9,
    float* __restrict__ out)
{
    __shared__ int2 s_shift;
    if (threadIdx.x == 0) {
        float best = -1.0f;
        int bi = 0;
        #pragma unroll
        for (int i = 0; i < 9; ++i) {
            float a = fabsf(w9[i]);
            if (a > best) { best = a; bi = i; }   // first occurrence wins (jnp.argmax)
        }
        s_shift = make_int2(bi / 3 - 1, bi % 3 - 1);
    }
    __syncthreads();
    const int dy = s_shift.x;
    const int dx = s_shift.y;

    const int gw   = (blockIdx.x * blockDim.x + threadIdx.x) >> 5;  // row id
    const int lane = threadIdx.x & 31;

    const int h  = gw & 255;                   // row within plane
    const int sh = h + dy;
    const size_t plane = (size_t)(gw >> 8);    // fused b*c plane

    float4 o0, o1;
    if ((unsigned)sh < 256u) {                 // warp-uniform
        const float4* src = reinterpret_cast<const float4*>(
            x + ((plane << 8) + (size_t)sh) * 256) + (lane << 1);
        float4 r0 = src[0];
        float4 r1 = src[1];
        if (dx == 0) {
            o0 = r0; o1 = r1;
        } else if (dx > 0) {
            float nxt = __shfl_down_sync(0xffffffffu, r0.x, 1);
            if (lane == 31) nxt = 0.0f;        // col 256 -> zero pad
            o0 = make_float4(r0.y, r0.z, r0.w, r1.x);
            o1 = make_float4(r1.y, r1.z, r1.w, nxt);
        } else {
            float prv = __shfl_up_sync(0xffffffffu, r1.w, 1);
            if (lane == 0) prv = 0.0f;         // col -1 -> zero pad
            o0 = make_float4(prv, r0.x, r0.y, r0.z);
            o1 = make_float4(r0.w, r1.x, r1.y, r1.z);
        }
    } else {
        o0 = make_float4(0.f, 0.f, 0.f, 0.f);
        o1 = o0;
    }

    float4* dst = reinterpret_cast<float4*>(out) + ((size_t)gw << 6) + (lane << 1);
    dst[0] = o0;
    dst[1] = o1;
}

extern "C" void kernel_launch(void* const* d_in, const int* in_sizes, int n_in,
                              void* d_out, int out_size) {
    const float* x = (const float*)d_in[0];
    const float* w = (const float*)d_in[1];
    float* out = (float*)d_out;

    int nrows  = out_size >> 8;     // 262144 rows
    int blocks = nrows >> 3;        // 8 warps (rows) per 256-thread block
    shift_row_kernel<<<blocks, 256>>>(x, w, out);
}

// round 13
// speedup vs baseline: 1.1329x; 1.0047x over previous
#include <cuda_runtime.h>

// Depthwise 3x3 conv with hard-one-hot kernel == pure spatial shift, zero pad:
//   out[b,c,h,w] = x[b,c, h+dy, w+dx],  (dy,dx) = argmax(|weight|) - 1
//
// Session-best structure (R2): one warp per image row, 2 aligned float4 per
// lane, horizontal +-1 shift via register shuffle (value shuffled past lane
// 0/31 is exactly the zero padding), argmax once per block via smem.
// R13 probe: 512-thread blocks (16 warps) — halves block count and the
// argmax+barrier preamble instances; occupancy unchanged (threads-limited).

__global__ __launch_bounds__(512) void shift_row_kernel(
    const float* __restrict__ x, const float* __restrict__ w9,
    float* __restrict__ out)
{
    __shared__ int2 s_shift;
    if (threadIdx.x == 0) {
        float best = -1.0f;
        int bi = 0;
        #pragma unroll
        for (int i = 0; i < 9; ++i) {
            float a = fabsf(w9[i]);
            if (a > best) { best = a; bi = i; }   // first occurrence wins (jnp.argmax)
        }
        s_shift = make_int2(bi / 3 - 1, bi % 3 - 1);
    }
    __syncthreads();
    const int dy = s_shift.x;
    const int dx = s_shift.y;

    const int gw   = (blockIdx.x * blockDim.x + threadIdx.x) >> 5;  // row id
    const int lane = threadIdx.x & 31;

    const int h  = gw & 255;                   // row within plane
    const int sh = h + dy;
    const size_t plane = (size_t)(gw >> 8);    // fused b*c plane

    float4 o0, o1;
    if ((unsigned)sh < 256u) {                 // warp-uniform
        const float4* src = reinterpret_cast<const float4*>(
            x + ((plane << 8) + (size_t)sh) * 256) + (lane << 1);
        float4 r0 = src[0];
        float4 r1 = src[1];
        if (dx == 0) {
            o0 = r0; o1 = r1;
        } else if (dx > 0) {
            float nxt = __shfl_down_sync(0xffffffffu, r0.x, 1);
            if (lane == 31) nxt = 0.0f;        // col 256 -> zero pad
            o0 = make_float4(r0.y, r0.z, r0.w, r1.x);
            o1 = make_float4(r1.y, r1.z, r1.w, nxt);
        } else {
            float prv = __shfl_up_sync(0xffffffffu, r1.w, 1);
            if (lane == 0) prv = 0.0f;         // col -1 -> zero pad
            o0 = make_float4(prv, r0.x, r0.y, r0.z);
            o1 = make_float4(r0.w, r1.x, r1.y, r1.z);
        }
    } else {
        o0 = make_float4(0.f, 0.f, 0.f, 0.f);
        o1 = o0;
    }

    float4* dst = reinterpret_cast<float4*>(out) + ((size_t)gw << 6) + (lane << 1);
    dst[0] = o0;
    dst[1] = o1;
}

extern "C" void kernel_launch(void* const* d_in, const int* in_sizes, int n_in,
                              void* d_out, int out_size) {
    const float* x = (const float*)d_in[0];
    const float* w = (const float*)d_in[1];
    float* out = (float*)d_out;

    int nrows  = out_size >> 8;     // 262144 rows
    int blocks = nrows >> 4;        // 16 warps (rows) per 512-thread block
    shift_row_kernel<<<blocks, 512>>>(x, w, out);
}

// round 14
// speedup vs baseline: 1.1509x; 1.0159x over previous
#include <cuda_runtime.h>

// Depthwise 3x3 conv with hard-one-hot kernel == pure spatial shift, zero pad:
//   out[b,c,h,w] = x[b,c, h+dy, w+dx],  (dy,dx) = argmax(|weight|) - 1
//
// Session-best structure (R2): one warp per image row, 2 aligned float4 per
// lane, horizontal +-1 shift via register shuffle (value shuffled past lane
// 0/31 is exactly the zero padding), argmax once per block via smem.
// R14 probe: 1024-thread blocks (32 warps, 8192 blocks) — block-count sweep
// continues; occupancy still threads-limited (2 blocks/SM), kernel shape
// unchanged, only launch/raster overhead in play.

__global__ __launch_bounds__(1024) void shift_row_kernel(
    const float* __restrict__ x, const float* __restrict__ w9,
    float* __restrict__ out)
{
    __shared__ int2 s_shift;
    if (threadIdx.x == 0) {
        float best = -1.0f;
        int bi = 0;
        #pragma unroll
        for (int i = 0; i < 9; ++i) {
            float a = fabsf(w9[i]);
            if (a > best) { best = a; bi = i; }   // first occurrence wins (jnp.argmax)
        }
        s_shift = make_int2(bi / 3 - 1, bi % 3 - 1);
    }
    __syncthreads();
    const int dy = s_shift.x;
    const int dx = s_shift.y;

    const int gw   = (blockIdx.x * blockDim.x + threadIdx.x) >> 5;  // row id
    const int lane = threadIdx.x & 31;

    const int h  = gw & 255;                   // row within plane
    const int sh = h + dy;
    const size_t plane = (size_t)(gw >> 8);    // fused b*c plane

    float4 o0, o1;
    if ((unsigned)sh < 256u) {                 // warp-uniform
        const float4* src = reinterpret_cast<const float4*>(
            x + ((plane << 8) + (size_t)sh) * 256) + (lane << 1);
        float4 r0 = src[0];
        float4 r1 = src[1];
        if (dx == 0) {
            o0 = r0; o1 = r1;
        } else if (dx > 0) {
            float nxt = __shfl_down_sync(0xffffffffu, r0.x, 1);
            if (lane == 31) nxt = 0.0f;        // col 256 -> zero pad
            o0 = make_float4(r0.y, r0.z, r0.w, r1.x);
            o1 = make_float4(r1.y, r1.z, r1.w, nxt);
        } else {
            float prv = __shfl_up_sync(0xffffffffu, r1.w, 1);
            if (lane == 0) prv = 0.0f;         // col -1 -> zero pad
            o0 = make_float4(prv, r0.x, r0.y, r0.z);
            o1 = make_float4(r0.w, r1.x, r1.y, r1.z);
        }
    } else {
        o0 = make_float4(0.f, 0.f, 0.f, 0.f);
        o1 = o0;
    }

    float4* dst = reinterpret_cast<float4*>(out) + ((size_t)gw << 6) + (lane << 1);
    dst[0] = o0;
    dst[1] = o1;
}

extern "C" void kernel_launch(void* const* d_in, const int* in_sizes, int n_in,
                              void* d_out, int out_size) {
    const float* x = (const float*)d_in[0];
    const float* w = (const float*)d_in[1];
    float* out = (float*)d_out;

    int nrows  = out_size >> 8;     // 262144 rows
    int blocks = nrows >> 5;        // 32 warps (rows) per 1024-thread block
    shift_row_kernel<<<blocks, 1024>>>(x, w, out);
}